// round 10
// baseline (speedup 1.0000x reference)
#include <cuda_runtime.h>
#include <math.h>

typedef unsigned long long u64;

#define BATCH  512
#define TLEN   1024
#define HID    64
#define M_TOTAL (BATCH*TLEN)
#define CHUNKS 8
#define CT     (TLEN/CHUNKS)          // 128 steps per chunk

#define NBLK        592               // 4 blocks/SM x 148 SMs: all resident (required)
#define NG          512               // gemm tasks per (l,c)  (1 batch row each)
#define NS          256               // scan tasks per (l,c)  (2 batch rows each)
#define TOTAL_TASKS (32*(NG+NS) + CHUNKS*NG)   // 28672

// Per-layer scratch.
__device__ __align__(16) float g_pre [4][M_TOTAL*HID];
__device__ __align__(16) float g_hout[4][M_TOTAL*HID];
__device__ __align__(16) float g_hst [4][BATCH*HID];    // h carry between chunks

// Dependency flags.
__device__ int gflag [4][CHUNKS][BATCH];   // pre(l,c,row) ready
__device__ int sflag2[4][CHUNKS][NS];      // h(l,c, 2-row group) ready

__device__ __forceinline__ int ld_acq(const int* p) {
    int v;
    asm volatile("ld.acquire.gpu.global.b32 %0, [%1];" : "=r"(v) : "l"(p) : "memory");
    return v;
}
__device__ __forceinline__ void st_rel(int* p, int v) {
    asm volatile("st.release.gpu.global.b32 [%0], %1;" :: "l"(p), "r"(v) : "memory");
}
__device__ __forceinline__ void bar_sync(int id) {
    asm volatile("bar.sync %0, 64;" :: "r"(id) : "memory");
}

__device__ __forceinline__ u64 pk2(float x, float y) {
    u64 r; asm("mov.b64 %0,{%1,%2};" : "=l"(r) : "f"(x), "f"(y)); return r;
}
__device__ __forceinline__ void upk2(u64 v, float &x, float &y) {
    asm("mov.b64 {%0,%1},%2;" : "=f"(x), "=f"(y) : "l"(v));
}
#define FMA2(d,a,b,c) asm("fma.rn.f32x2 %0,%1,%2,%3;" : "=l"(d) : "l"(a), "l"(b), "l"(c))
#define ADD2(d,a,b)   asm("add.rn.f32x2 %0,%1,%2;"    : "=l"(d) : "l"(a), "l"(b))

__device__ __forceinline__ float tanh_fast(float x) {
    float xc = fminf(fmaxf(x, -15.0f), 15.0f);
    float e;
    asm("ex2.approx.f32 %0, %1;" : "=f"(e) : "f"(xc * 2.885390081777927f));
    float r;
    asm("rcp.approx.f32 %0, %1;" : "=f"(r) : "f"(e + 1.0f));
    return (e - 1.0f) * r;
}

// Shared memory union: gemm tile staging vs scan h buffers.
struct SmemGemm {
    u64 Xd[128*32];   // 32 KB
    u64 Wp[32*32];    // 8 KB
};
struct SmemScan {
    float hbuf[2][2][64];   // [row][phase][col]
};
union SmemU {
    SmemGemm g;
    SmemScan s;
};

// ============================================================================
// GEMM tile body (proven): 128 threads, 128 rows x 64 cols, 8x8 per thread.
// ============================================================================
__device__ __forceinline__ void gemm_body(
    SmemGemm& sm,
    const float* __restrict__ X, const float* __restrict__ W,
    const float* __restrict__ b1, const float* __restrict__ b2,
    float* __restrict__ Out, int K, long m0)
{
    u64* Xd = sm.Xd;
    u64* Wp = sm.Wp;

    const int tid = threadIdx.x;
    const int nt  = tid & 7;
    const int mt  = tid >> 3;
    const int np0 = nt * 4;
    const int mr  = mt * 8;
    const int xsw = (mt & 3) << 2;

    u64 acc[8][4];
    {
        u64 bias[4];
        #pragma unroll
        for (int p = 0; p < 4; p++) {
            int n = (np0 + p) * 2;
            float v0 = b1[n], v1 = b1[n+1];
            if (b2) { v0 += b2[n]; v1 += b2[n+1]; }
            bias[p] = pk2(v0, v1);
        }
        #pragma unroll
        for (int i = 0; i < 8; i++)
            #pragma unroll
            for (int p = 0; p < 4; p++) acc[i][p] = bias[p];
    }

    #pragma unroll
    for (int kh = 0; kh < 2; kh++) {
        const int kbase = kh * 32;
        __syncthreads();

        #pragma unroll 8
        for (int i = 0; i < 32; i++) {
            int idx = i * 128 + tid;
            int m  = idx >> 5;
            int kk = idx & 31;
            int k  = kbase + kk;
            float v = (k < K) ? X[(m0 + m) * (long)K + k] : 0.f;
            Xd[m * 32 + (kk ^ (((m >> 3) & 3) << 2))] = pk2(v, v);
        }
        #pragma unroll
        for (int i = 0; i < 8; i++) {
            int idx = i * 128 + tid;
            int np = idx >> 5;
            int kk = idx & 31;
            int k  = kbase + kk;
            float w0 = 0.f, w1 = 0.f;
            if (k < K) {
                w0 = W[(2*np)   * (long)K + k];
                w1 = W[(2*np+1) * (long)K + k];
            }
            Wp[kk * 32 + (np ^ ((kk & 7) << 2))] = pk2(w0, w1);
        }
        __syncthreads();

        #pragma unroll 8
        for (int kk = 0; kk < 32; kk++) {
            int wbase = kk * 32 + (np0 ^ ((kk & 7) << 2));
            ulonglong2 wA = *reinterpret_cast<const ulonglong2*>(&Wp[wbase]);
            ulonglong2 wB = *reinterpret_cast<const ulonglong2*>(&Wp[wbase + 2]);
            const u64* xcol = &Xd[mr * 32 + (kk ^ xsw)];
            #pragma unroll
            for (int i = 0; i < 8; i++) {
                u64 xv = xcol[i * 32];
                FMA2(acc[i][0], xv, wA.x, acc[i][0]);
                FMA2(acc[i][1], xv, wA.y, acc[i][1]);
                FMA2(acc[i][2], xv, wB.x, acc[i][2]);
                FMA2(acc[i][3], xv, wB.y, acc[i][3]);
            }
        }
    }

    const int n0 = np0 * 2;
    #pragma unroll
    for (int i = 0; i < 8; i++) {
        float* dst = &Out[(m0 + mr + i) * 64 + n0];
        ulonglong2 v0, v1;
        v0.x = acc[i][0]; v0.y = acc[i][1];
        v1.x = acc[i][2]; v1.y = acc[i][3];
        *reinterpret_cast<ulonglong2*>(dst)     = v0;
        *reinterpret_cast<ulonglong2*>(dst + 4) = v1;
    }
}

__global__ void zero_flags()
{
    int idx = blockIdx.x * blockDim.x + threadIdx.x;
    const int NGf = 4 * CHUNKS * BATCH;
    const int NSf = 4 * CHUNKS * NS;
    if (idx < NGf) (&gflag [0][0][0])[idx] = 0;
    if (idx < NSf) (&sflag2[0][0][0])[idx] = 0;
}

// ============================================================================
// Persistent-block wavefront. Tasks in global topological (diagonal) order:
//   d = 0..10: for l = max(0,d-7)..min(3,d), c = d-l:
//                [ NG gemm(l,c,b) ][ NS scan(l,c,g) ]
//              then (d>=3): [ NG fc(c=d-3,b) ]
// Task k -> block k % NBLK, processed in increasing k. With all NBLK blocks
// resident (4/SM x 148), the minimal-unfinished-task induction guarantees
// forward progress (deps of task k have global index < k).
// ============================================================================
__global__ void __launch_bounds__(128, 4) mega(
    const float* __restrict__ x,
    const float* __restrict__ Wih0, const float* __restrict__ Whh0,
    const float* __restrict__ bih0, const float* __restrict__ bhh0,
    const float* __restrict__ Wih,  const float* __restrict__ Whh,
    const float* __restrict__ bih,  const float* __restrict__ bhh,
    const float* __restrict__ Wfc,  const float* __restrict__ bfc,
    float* __restrict__ out)
{
    __shared__ SmemU sm;
    const int tid = threadIdx.x;

    #pragma unroll 1
    for (int k = blockIdx.x; k < TOTAL_TASKS; k += NBLK) {
        // ---- decode task k -> (kind, l, c, idx)
        int kind = -1, l = 0, c = 0, idx = 0;
        {
            int base = 0;
            #pragma unroll 1
            for (int d = 0; d <= 10 && kind < 0; d++) {
                int lmin = (d > 7) ? d - 7 : 0;
                int lmax = (d < 3) ? d : 3;
                int pairs = lmax - lmin + 1;
                int cnt = pairs * (NG + NS) + ((d >= 3) ? NG : 0);
                if (k < base + cnt) {
                    int rem = k - base;
                    #pragma unroll 1
                    for (int ll = lmin; ll <= lmax && kind < 0; ll++) {
                        if (rem < NG) { kind = 0; l = ll; c = d - ll; idx = rem; break; }
                        rem -= NG;
                        if (rem < NS) { kind = 1; l = ll; c = d - ll; idx = rem; break; }
                        rem -= NS;
                    }
                    if (kind < 0) { kind = 2; c = d - 3; idx = rem; }
                }
                base += cnt;
            }
        }
        const int t0 = c * CT;
        __syncthreads();   // task boundary (smem reuse)

        if (kind == 0 || kind == 2) {
            // ================= GEMM / FC: one 128-row tile (batch row idx) ======
            const int b = idx;
            if (tid == 0) {
                if (kind == 2)      { while (ld_acq(&sflag2[3][c][b>>1])   == 0) __nanosleep(128); __threadfence(); }
                else if (l > 0)     { while (ld_acq(&sflag2[l-1][c][b>>1]) == 0) __nanosleep(128); __threadfence(); }
            }
            __syncthreads();

            const float* X; const float* W; const float* b1; const float* b2;
            float* Out; int K;
            if (kind == 2) {
                X = &g_hout[3][0]; W = Wfc; b1 = bfc; b2 = nullptr; Out = out; K = 64;
            } else if (l == 0) {
                X = x; W = Wih0; b1 = bih0; b2 = bhh0; Out = &g_pre[0][0]; K = 52;
            } else {
                X = &g_hout[l-1][0]; W = Wih + (l-1)*4096;
                b1 = bih + (l-1)*64;  b2 = bhh + (l-1)*64;
                Out = &g_pre[l][0]; K = 64;
            }
            gemm_body(sm.g, X, W, b1, b2, Out, K, (long)b * TLEN + t0);

            if (kind == 0) {
                __threadfence();
                __syncthreads();
                if (tid == 0) st_rel(&gflag[l][c][b], 1);
            }
            continue;
        }

        // ================= SCAN: 2 independent row-engines (named barriers) =====
        const int g = idx;
        const float* Whh_l = (l == 0) ? Whh0 : Whh + (l-1)*4096;
        float* pre  = &g_pre [l][0];
        float* hout = &g_hout[l][0];
        float* hst  = &g_hst [l][0];

        const int r    = tid >> 6;            // row engine (0/1)
        const int u    = tid & 63;
        const int W32  = u >> 5;              // warp-half: outputs [32W, 32W+32)
        const int lane = tid & 31;
        const int og   = lane & 7;            // output group of 4
        const int ks   = lane >> 3;           // k-quarter
        const int K0   = 16 * ks;
        const int jo   = 32*W32 + 4*og + ks;  // output this lane finalizes
        const long b   = 2L*g + r;
        const int bar  = 1 + r;

        if (u == 0) {
            while (ld_acq(&gflag[l][c][b]) == 0) __nanosleep(128);
            if (c > 0) while (ld_acq(&sflag2[l][c-1][g]) == 0) __nanosleep(128);
            __threadfence();
        }
        bar_sync(bar);

        float h0v = (c == 0) ? 0.f : __ldcg(&hst[b*64 + u]);
        sm.s.hbuf[r][0][u] = h0v;
        sm.s.hbuf[r][1][u] = h0v;

        u64 w2[4][8];
        #pragma unroll
        for (int o = 0; o < 4; o++) {
            const float4* wr = reinterpret_cast<const float4*>(Whh_l + (32*W32 + 4*og + o)*64 + K0);
            #pragma unroll
            for (int q = 0; q < 4; q++) {
                float4 w = __ldg(&wr[q]);
                w2[o][2*q]   = pk2(w.x, w.y);
                w2[o][2*q+1] = pk2(w.z, w.w);
            }
        }

        const float* prow = pre  + (b * TLEN + t0) * 64 + jo;
        float*       orow = hout + (b * TLEN + t0) * 64 + jo;

        float pb[8];
        #pragma unroll
        for (int q = 0; q < 8; q++) pb[q] = __ldg(&prow[q * 64]);
        bar_sync(bar);

        #pragma unroll 8
        for (int t = 0; t < CT; t++) {
            float cur = pb[t & 7];
            if (t + 8 < CT) pb[t & 7] = __ldg(&prow[(long)(t + 8) * 64]);

            const ulonglong2* H2 = reinterpret_cast<const ulonglong2*>(&sm.s.hbuf[r][t & 1][K0]);
            ulonglong2 hA = H2[0];
            ulonglong2 hB = H2[1];
            ulonglong2 hC = H2[2];
            ulonglong2 hD = H2[3];

            float P[4];
            #pragma unroll
            for (int o = 0; o < 4; o++) {
                u64 a0 = 0ull, a1 = 0ull;
                FMA2(a0, hA.x, w2[o][0], a0);
                FMA2(a1, hA.y, w2[o][1], a1);
                FMA2(a0, hB.x, w2[o][2], a0);
                FMA2(a1, hB.y, w2[o][3], a1);
                FMA2(a0, hC.x, w2[o][4], a0);
                FMA2(a1, hC.y, w2[o][5], a1);
                FMA2(a0, hD.x, w2[o][6], a0);
                FMA2(a1, hD.y, w2[o][7], a1);
                ADD2(a0, a0, a1);
                float lo, hi; upk2(a0, lo, hi);
                P[o] = lo + hi;
            }
            #pragma unroll
            for (int o = 0; o < 4; o++) {
                P[o] += __shfl_xor_sync(0xffffffffu, P[o], 8);
                P[o] += __shfl_xor_sync(0xffffffffu, P[o], 16);
            }
            float sum = (ks == 0) ? P[0] : (ks == 1) ? P[1] : (ks == 2) ? P[2] : P[3];
            float h = tanh_fast(cur + sum);

            orow[(long)t * 64] = h;
            sm.s.hbuf[r][(t & 1) ^ 1][jo] = h;
            bar_sync(bar);
        }

        hst[b*64 + jo] = sm.s.hbuf[r][0][jo];   // CT even -> final h in phase 0

        __threadfence();
        __syncthreads();                        // join both engines
        if (tid == 0) st_rel(&sflag2[l][c][g], 1);
    }
}

extern "C" void kernel_launch(void* const* d_in, const int* in_sizes, int n_in,
                              void* d_out, int out_size)
{
    const float* x    = (const float*)d_in[0];
    const float* Wih0 = (const float*)d_in[1];
    const float* Whh0 = (const float*)d_in[2];
    const float* bih0 = (const float*)d_in[3];
    const float* bhh0 = (const float*)d_in[4];
    const float* Wih  = (const float*)d_in[5];
    const float* Whh  = (const float*)d_in[6];
    const float* bih  = (const float*)d_in[7];
    const float* bhh  = (const float*)d_in[8];
    const float* Wfc  = (const float*)d_in[9];
    const float* bfc  = (const float*)d_in[10];
    float* out = (float*)d_out;

    zero_flags<<<(4*CHUNKS*BATCH + 255)/256, 256>>>();
    mega<<<NBLK, 128>>>(x, Wih0, Whh0, bih0, bhh0,
                        Wih, Whh, bih, bhh, Wfc, bfc, out);
}

// round 11
// speedup vs baseline: 1.2395x; 1.2395x over previous
#include <cuda_runtime.h>
#include <math.h>

typedef unsigned long long u64;

#define BATCH  512
#define TLEN   1024
#define HID    64
#define M_TOTAL (BATCH*TLEN)
#define CHUNKS 8
#define CT     (TLEN/CHUNKS)          // 128 steps per chunk

#define NBLK        592               // 4 blocks/SM x 148 SMs: all resident
#define NG          512               // gemm tasks per (l,c)  (1 batch row each)
#define NS          256               // scan tasks per (l,c)  (2 batch rows each)
#define TOTAL_TASKS (32*(NG+NS) + CHUNKS*NG)   // 28672

// Per-layer scratch.
__device__ __align__(16) float g_pre [4][M_TOTAL*HID];
__device__ __align__(16) float g_hout[4][M_TOTAL*HID];
__device__ __align__(16) float g_hst [4][BATCH*HID];    // h carry between chunks

// Dependency flags + dynamic task ticket.
__device__ int gflag [4][CHUNKS][BATCH];   // pre(l,c,row) ready
__device__ int sflag2[4][CHUNKS][NS];      // h(l,c, 2-row group) ready
__device__ unsigned g_task_ctr;

__device__ __forceinline__ int ld_acq(const int* p) {
    int v;
    asm volatile("ld.acquire.gpu.global.b32 %0, [%1];" : "=r"(v) : "l"(p) : "memory");
    return v;
}
__device__ __forceinline__ void st_rel(int* p, int v) {
    asm volatile("st.release.gpu.global.b32 [%0], %1;" :: "l"(p), "r"(v) : "memory");
}
__device__ __forceinline__ void bar_sync(int id) {
    asm volatile("bar.sync %0, 64;" :: "r"(id) : "memory");
}

__device__ __forceinline__ u64 pk2(float x, float y) {
    u64 r; asm("mov.b64 %0,{%1,%2};" : "=l"(r) : "f"(x), "f"(y)); return r;
}
__device__ __forceinline__ void upk2(u64 v, float &x, float &y) {
    asm("mov.b64 {%0,%1},%2;" : "=f"(x), "=f"(y) : "l"(v));
}
#define FMA2(d,a,b,c) asm("fma.rn.f32x2 %0,%1,%2,%3;" : "=l"(d) : "l"(a), "l"(b), "l"(c))
#define ADD2(d,a,b)   asm("add.rn.f32x2 %0,%1,%2;"    : "=l"(d) : "l"(a), "l"(b))

__device__ __forceinline__ float tanh_fast(float x) {
    float xc = fminf(fmaxf(x, -15.0f), 15.0f);
    float e;
    asm("ex2.approx.f32 %0, %1;" : "=f"(e) : "f"(xc * 2.885390081777927f));
    float r;
    asm("rcp.approx.f32 %0, %1;" : "=f"(r) : "f"(e + 1.0f));
    return (e - 1.0f) * r;
}

// Shared memory union: gemm tile staging vs scan h buffers.
struct SmemGemm {
    u64 Xd[128*32];   // 32 KB
    u64 Wp[32*32];    // 8 KB
};
struct SmemScan {
    float hbuf[2][2][64];   // [row][phase][col]
};
union SmemU {
    SmemGemm g;
    SmemScan s;
};

// ============================================================================
// GEMM tile body (proven): 128 threads, 128 rows x 64 cols, 8x8 per thread.
// ============================================================================
__device__ __forceinline__ void gemm_body(
    SmemGemm& sm,
    const float* __restrict__ X, const float* __restrict__ W,
    const float* __restrict__ b1, const float* __restrict__ b2,
    float* __restrict__ Out, int K, long m0)
{
    u64* Xd = sm.Xd;
    u64* Wp = sm.Wp;

    const int tid = threadIdx.x;
    const int nt  = tid & 7;
    const int mt  = tid >> 3;
    const int np0 = nt * 4;
    const int mr  = mt * 8;
    const int xsw = (mt & 3) << 2;

    u64 acc[8][4];
    {
        u64 bias[4];
        #pragma unroll
        for (int p = 0; p < 4; p++) {
            int n = (np0 + p) * 2;
            float v0 = b1[n], v1 = b1[n+1];
            if (b2) { v0 += b2[n]; v1 += b2[n+1]; }
            bias[p] = pk2(v0, v1);
        }
        #pragma unroll
        for (int i = 0; i < 8; i++)
            #pragma unroll
            for (int p = 0; p < 4; p++) acc[i][p] = bias[p];
    }

    #pragma unroll
    for (int kh = 0; kh < 2; kh++) {
        const int kbase = kh * 32;
        __syncthreads();

        #pragma unroll 8
        for (int i = 0; i < 32; i++) {
            int idx = i * 128 + tid;
            int m  = idx >> 5;
            int kk = idx & 31;
            int k  = kbase + kk;
            float v = (k < K) ? X[(m0 + m) * (long)K + k] : 0.f;
            Xd[m * 32 + (kk ^ (((m >> 3) & 3) << 2))] = pk2(v, v);
        }
        #pragma unroll
        for (int i = 0; i < 8; i++) {
            int idx = i * 128 + tid;
            int np = idx >> 5;
            int kk = idx & 31;
            int k  = kbase + kk;
            float w0 = 0.f, w1 = 0.f;
            if (k < K) {
                w0 = W[(2*np)   * (long)K + k];
                w1 = W[(2*np+1) * (long)K + k];
            }
            Wp[kk * 32 + (np ^ ((kk & 7) << 2))] = pk2(w0, w1);
        }
        __syncthreads();

        #pragma unroll 8
        for (int kk = 0; kk < 32; kk++) {
            int wbase = kk * 32 + (np0 ^ ((kk & 7) << 2));
            ulonglong2 wA = *reinterpret_cast<const ulonglong2*>(&Wp[wbase]);
            ulonglong2 wB = *reinterpret_cast<const ulonglong2*>(&Wp[wbase + 2]);
            const u64* xcol = &Xd[mr * 32 + (kk ^ xsw)];
            #pragma unroll
            for (int i = 0; i < 8; i++) {
                u64 xv = xcol[i * 32];
                FMA2(acc[i][0], xv, wA.x, acc[i][0]);
                FMA2(acc[i][1], xv, wA.y, acc[i][1]);
                FMA2(acc[i][2], xv, wB.x, acc[i][2]);
                FMA2(acc[i][3], xv, wB.y, acc[i][3]);
            }
        }
    }

    const int n0 = np0 * 2;
    #pragma unroll
    for (int i = 0; i < 8; i++) {
        float* dst = &Out[(m0 + mr + i) * 64 + n0];
        ulonglong2 v0, v1;
        v0.x = acc[i][0]; v0.y = acc[i][1];
        v1.x = acc[i][2]; v1.y = acc[i][3];
        *reinterpret_cast<ulonglong2*>(dst)     = v0;
        *reinterpret_cast<ulonglong2*>(dst + 4) = v1;
    }
}

__global__ void zero_flags()
{
    int idx = blockIdx.x * blockDim.x + threadIdx.x;
    const int NGf = 4 * CHUNKS * BATCH;
    const int NSf = 4 * CHUNKS * NS;
    if (idx < NGf) (&gflag [0][0][0])[idx] = 0;
    if (idx < NSf) (&sflag2[0][0][0])[idx] = 0;
    if (idx == 0) g_task_ctr = 0u;
}

// ============================================================================
// Persistent-block wavefront with DYNAMIC work stealing. Topological task
// order (diagonals d = c + l, FC on diagonal c+3); blocks grab tasks via
// atomicAdd ticket. A block grabs only after finishing its previous task,
// so all lower-index tasks are held by live resident blocks -> deadlock-free.
// ============================================================================
__global__ void __launch_bounds__(128, 4) mega(
    const float* __restrict__ x,
    const float* __restrict__ Wih0, const float* __restrict__ Whh0,
    const float* __restrict__ bih0, const float* __restrict__ bhh0,
    const float* __restrict__ Wih,  const float* __restrict__ Whh,
    const float* __restrict__ bih,  const float* __restrict__ bhh,
    const float* __restrict__ Wfc,  const float* __restrict__ bfc,
    float* __restrict__ out)
{
    __shared__ SmemU sm;
    __shared__ unsigned s_task;
    const int tid = threadIdx.x;

    #pragma unroll 1
    for (;;) {
        __syncthreads();   // protect smem reuse (previous task fully done)
        if (tid == 0) s_task = atomicAdd(&g_task_ctr, 1u);
        __syncthreads();
        const unsigned k = s_task;
        if (k >= TOTAL_TASKS) break;

        // ---- decode task k -> (kind, l, c, idx) along diagonals
        int kind = -1, l = 0, c = 0, idx = 0;
        {
            int base = 0;
            #pragma unroll 1
            for (int d = 0; d <= 10 && kind < 0; d++) {
                int lmin = (d > 7) ? d - 7 : 0;
                int lmax = (d < 3) ? d : 3;
                int pairs = lmax - lmin + 1;
                int cnt = pairs * (NG + NS) + ((d >= 3) ? NG : 0);
                if ((int)k < base + cnt) {
                    int rem = (int)k - base;
                    #pragma unroll 1
                    for (int ll = lmin; ll <= lmax && kind < 0; ll++) {
                        if (rem < NG) { kind = 0; l = ll; c = d - ll; idx = rem; break; }
                        rem -= NG;
                        if (rem < NS) { kind = 1; l = ll; c = d - ll; idx = rem; break; }
                        rem -= NS;
                    }
                    if (kind < 0) { kind = 2; c = d - 3; idx = rem; }
                }
                base += cnt;
            }
        }
        const int t0 = c * CT;

        if (kind == 0 || kind == 2) {
            // ================= GEMM / FC: one 128-row tile (batch row idx) ======
            const int b = idx;
            if (tid == 0) {
                if (kind == 2)  { while (ld_acq(&sflag2[3][c][b>>1])   == 0) __nanosleep(128); __threadfence(); }
                else if (l > 0) { while (ld_acq(&sflag2[l-1][c][b>>1]) == 0) __nanosleep(128); __threadfence(); }
            }
            __syncthreads();

            const float* X; const float* W; const float* b1; const float* b2;
            float* Out; int K;
            if (kind == 2) {
                X = &g_hout[3][0]; W = Wfc; b1 = bfc; b2 = nullptr; Out = out; K = 64;
            } else if (l == 0) {
                X = x; W = Wih0; b1 = bih0; b2 = bhh0; Out = &g_pre[0][0]; K = 52;
            } else {
                X = &g_hout[l-1][0]; W = Wih + (l-1)*4096;
                b1 = bih + (l-1)*64;  b2 = bhh + (l-1)*64;
                Out = &g_pre[l][0]; K = 64;
            }
            gemm_body(sm.g, X, W, b1, b2, Out, K, (long)b * TLEN + t0);

            if (kind == 0) {
                __threadfence();
                __syncthreads();
                if (tid == 0) st_rel(&gflag[l][c][b], 1);
            }
            continue;
        }

        // ================= SCAN: 2 independent row-engines (named barriers) =====
        const int g = idx;
        const float* Whh_l = (l == 0) ? Whh0 : Whh + (l-1)*4096;
        float* pre  = &g_pre [l][0];
        float* hout = &g_hout[l][0];
        float* hst  = &g_hst [l][0];

        const int r    = tid >> 6;            // row engine (0/1)
        const int u    = tid & 63;
        const int W32  = u >> 5;              // warp-half: outputs [32W, 32W+32)
        const int lane = tid & 31;
        const int og   = lane & 7;            // output group of 4
        const int ks   = lane >> 3;           // k-quarter
        const int K0   = 16 * ks;
        const int jo   = 32*W32 + 4*og + ks;  // output this lane finalizes
        const long b   = 2L*g + r;
        const int bar  = 1 + r;

        if (u == 0) {
            while (ld_acq(&gflag[l][c][b]) == 0) __nanosleep(128);
            if (c > 0) while (ld_acq(&sflag2[l][c-1][g]) == 0) __nanosleep(128);
            __threadfence();
        }
        bar_sync(bar);

        float h0v = (c == 0) ? 0.f : __ldcg(&hst[b*64 + u]);
        sm.s.hbuf[r][0][u] = h0v;
        sm.s.hbuf[r][1][u] = h0v;

        u64 w2[4][8];
        #pragma unroll
        for (int o = 0; o < 4; o++) {
            const float4* wr = reinterpret_cast<const float4*>(Whh_l + (32*W32 + 4*og + o)*64 + K0);
            #pragma unroll
            for (int q = 0; q < 4; q++) {
                float4 w = __ldg(&wr[q]);
                w2[o][2*q]   = pk2(w.x, w.y);
                w2[o][2*q+1] = pk2(w.z, w.w);
            }
        }

        const float* prow = pre  + (b * TLEN + t0) * 64 + jo;
        float*       orow = hout + (b * TLEN + t0) * 64 + jo;

        float pb[8];
        #pragma unroll
        for (int q = 0; q < 8; q++) pb[q] = __ldg(&prow[q * 64]);
        bar_sync(bar);

        #pragma unroll 8
        for (int t = 0; t < CT; t++) {
            float cur = pb[t & 7];
            if (t + 8 < CT) pb[t & 7] = __ldg(&prow[(long)(t + 8) * 64]);

            const ulonglong2* H2 = reinterpret_cast<const ulonglong2*>(&sm.s.hbuf[r][t & 1][K0]);
            ulonglong2 hA = H2[0];
            ulonglong2 hB = H2[1];
            ulonglong2 hC = H2[2];
            ulonglong2 hD = H2[3];

            float P[4];
            #pragma unroll
            for (int o = 0; o < 4; o++) {
                u64 a0 = 0ull, a1 = 0ull;
                FMA2(a0, hA.x, w2[o][0], a0);
                FMA2(a1, hA.y, w2[o][1], a1);
                FMA2(a0, hB.x, w2[o][2], a0);
                FMA2(a1, hB.y, w2[o][3], a1);
                FMA2(a0, hC.x, w2[o][4], a0);
                FMA2(a1, hC.y, w2[o][5], a1);
                FMA2(a0, hD.x, w2[o][6], a0);
                FMA2(a1, hD.y, w2[o][7], a1);
                ADD2(a0, a0, a1);
                float lo, hi; upk2(a0, lo, hi);
                P[o] = lo + hi;
            }
            #pragma unroll
            for (int o = 0; o < 4; o++) {
                P[o] += __shfl_xor_sync(0xffffffffu, P[o], 8);
                P[o] += __shfl_xor_sync(0xffffffffu, P[o], 16);
            }
            float sum = (ks == 0) ? P[0] : (ks == 1) ? P[1] : (ks == 2) ? P[2] : P[3];
            float h = tanh_fast(cur + sum);

            orow[(long)t * 64] = h;
            sm.s.hbuf[r][(t & 1) ^ 1][jo] = h;
            bar_sync(bar);
        }

        hst[b*64 + jo] = sm.s.hbuf[r][0][jo];   // CT even -> final h in phase 0

        __threadfence();
        __syncthreads();                        // join both engines
        if (tid == 0) st_rel(&sflag2[l][c][g], 1);
    }
}

extern "C" void kernel_launch(void* const* d_in, const int* in_sizes, int n_in,
                              void* d_out, int out_size)
{
    const float* x    = (const float*)d_in[0];
    const float* Wih0 = (const float*)d_in[1];
    const float* Whh0 = (const float*)d_in[2];
    const float* bih0 = (const float*)d_in[3];
    const float* bhh0 = (const float*)d_in[4];
    const float* Wih  = (const float*)d_in[5];
    const float* Whh  = (const float*)d_in[6];
    const float* bih  = (const float*)d_in[7];
    const float* bhh  = (const float*)d_in[8];
    const float* Wfc  = (const float*)d_in[9];
    const float* bfc  = (const float*)d_in[10];
    float* out = (float*)d_out;

    zero_flags<<<(4*CHUNKS*BATCH + 255)/256, 256>>>();
    mega<<<NBLK, 128>>>(x, Wih0, Whh0, bih0, bhh0,
                        Wih, Whh, bih, bhh, Wfc, bfc, out);
}